// round 16
// baseline (speedup 1.0000x reference)
#include <cuda_runtime.h>
#include <cuda_bf16.h>
#include <math.h>
#include <stdint.h>

#define G   4096
#define NN  64
#define EE  256
#define FF  64
#define DD  128
#define EPN 32768

// ---------------- device scratch (static, no allocations) ----------------
__device__ float d_gembs[G * DD];
__device__ float d_deg[G];
__device__ float d_agg1[G * DD];
__device__ float d_h[G * 256];
__device__ float d_agg2[G * 256];
__device__ float d_mu[G * DD];
__device__ float d_ls[G * DD];
__device__ float d_zc[G * 256];
__device__ float d_zl1[G * 256];
__device__ float d_zl2[G * 256];
__device__ float d_sums[8];   // 0:pen 1:plog 2:nlog 3:kl
// transposed bf16 hi/lo weights [N][K]: Wg[0,8192) Wc1[8192,40960) Wmu[40960,73728)
// Wls[73728,106496) Wl1[106496,172032) Wl2[172032,237568) Wf1[237568,239616)
__device__ __nv_bfloat16 d_wth[239616];
__device__ __nv_bfloat16 d_wtl[239616];

// ---------------- helpers ----------------
__device__ __forceinline__ void mma_bf16(float* c, const uint32_t* a, const uint32_t* b) {
    asm volatile("mma.sync.aligned.m16n8k16.row.col.f32.bf16.bf16.f32 "
        "{%0,%1,%2,%3}, {%4,%5,%6,%7}, {%8,%9}, {%0,%1,%2,%3};"
        : "+f"(c[0]), "+f"(c[1]), "+f"(c[2]), "+f"(c[3])
        : "r"(a[0]), "r"(a[1]), "r"(a[2]), "r"(a[3]), "r"(b[0]), "r"(b[1]));
}
__device__ __forceinline__ void cvt_split2(float x, float y, uint32_t& hi, uint32_t& lo) {
    __nv_bfloat162 h = __floats2bfloat162_rn(x, y);
    float rx = x - __bfloat162float(h.x);
    float ry = y - __bfloat162float(h.y);
    __nv_bfloat162 l = __floats2bfloat162_rn(rx, ry);
    hi = *(uint32_t*)&h;
    lo = *(uint32_t*)&l;
}

// ---------------- zero scratch accumulators + graph-level degree ----------------
__global__ void k_zero(const int* __restrict__ pe) {
    int i = blockIdx.x * blockDim.x + threadIdx.x;
    int stride = gridDim.x * blockDim.x;
    for (int j = i; j < G * 256; j += stride) d_agg2[j] = 0.f;
    for (int j = i; j < G * DD; j += stride) d_agg1[j] = 0.f;
    for (int j = i; j < G; j += stride) d_deg[j] = 0.f;
    if (i < 8) d_sums[i] = 0.f;
}
__global__ void k_deg(const int* __restrict__ pe) {
    int i = blockIdx.x * blockDim.x + threadIdx.x;
    if (i < EPN) atomicAdd(&d_deg[pe[EPN + i]], 1.0f);
}
__global__ void k_dinv() {
    int i = blockIdx.x * blockDim.x + threadIdx.x;
    if (i < G) d_deg[i] = rsqrtf(d_deg[i] + 1.0f);
}

// ---------------- weight transpose + bf16 hi/lo split ----------------
__global__ void k_prepw(const float* __restrict__ W0, const float* __restrict__ W1,
                        const float* __restrict__ W2, const float* __restrict__ W3,
                        const float* __restrict__ W4, const float* __restrict__ W5,
                        const float* __restrict__ W6) {
    const float* Ws[7] = {W0, W1, W2, W3, W4, W5, W6};
    const int Ks[7] = {64, 128, 256, 256, 256, 256, 128};
    const int Ns[7] = {128, 256, 128, 128, 256, 256, 16};
    const int offs[8] = {0, 8192, 40960, 73728, 106496, 172032, 237568, 239616};
    int i = blockIdx.x * blockDim.x + threadIdx.x;
    if (i >= 239616) return;
    int s = 0;
    while (i >= offs[s + 1]) s++;
    int local = i - offs[s];
    int K = Ks[s], N = Ns[s];
    int n = local / K, k = local - n * K;
    float v = Ws[s][k * N + n];
    __nv_bfloat16 h = __float2bfloat16(v);
    d_wth[i] = h;
    d_wtl[i] = __float2bfloat16(v - __bfloat162float(h));
}

// ---------------- fully fused per-graph kernel (1 graph / block) ----------------
// Nx = N @ x, then h = Nx @ Wg (HMMA split); g_emb from fragments; 8-warp a1 head.
// dyn smem 38912 B; __launch_bounds__(256,4) -> 4 CTAs/SM (32 warps).
#define XTS 72
#define TST 72
#define HST 136
__global__ void __launch_bounds__(256, 4) k_xwagg(
    const float* __restrict__ x, const int* __restrict__ ei, const float* __restrict__ ew,
    const float* __restrict__ bg, const float* __restrict__ bf1,
    const float* __restrict__ Wf2, const float* __restrict__ bf2)
{
    extern __shared__ char dyn[];
    __nv_bfloat16* sXTh = (__nv_bfloat16*)dyn;          // [64 f][XTS], [0,18432)
    __nv_bfloat16* sXTl = sXTh + 64 * XTS;
    float* Nf = (float*)(dyn + 18432);                  // [64][64] f32 (transient)
    __nv_bfloat16* sNbh = (__nv_bfloat16*)(dyn + 18432);// [64][TST] (aliases Nf)
    __nv_bfloat16* sNbl = sNbh + 64 * TST;              // ends 36864
    __nv_bfloat16* sNxh = (__nv_bfloat16*)dyn;          // [64 n][TST] (aliases xT)
    __nv_bfloat16* sNxl = sNxh + 64 * TST;
    __nv_bfloat16* sWh = (__nv_bfloat16*)(dyn + 18432); // [128 c][40], ends 38912
    __nv_bfloat16* sWl = sWh + 128 * 40;
    __nv_bfloat16* shh = (__nv_bfloat16*)dyn;           // [64][HST], ends 34816
    __nv_bfloat16* shl = shh + 64 * HST;

    __shared__ float sdeg[NN], sdinv[NN], sdeg2[NN], sdv2[NN];
    __shared__ float sbias[DD];
    __shared__ float sS[NN * 2];
    __shared__ float sgpart[DD];
    __shared__ float sped[4];
    __shared__ float sLog[2][NN][2];   // nt-half x row x {l0,l1}

    int t = threadIdx.x, lane = t & 31, warp = t >> 5;
    int g = blockIdx.x;
    const float* A = x + (size_t)g * NN * FF;

    // ---- phase 0: edges, init ----
    int e_es = ei[(size_t)g * 512 + t];
    int e_ed = ei[(size_t)g * 512 + 256 + t];
    float e_w = ew[(size_t)g * 256 + t];
    if (t < NN) { sdeg[t] = 0.f; sdeg2[t] = 0.f; }
    if (t < DD) { sbias[t] = bg[t]; sgpart[t] = 0.f; }
    if (t < 4) sped[t] = 0.f;
#pragma unroll
    for (int j = 0; j < 16; j++) Nf[t + j * 256] = 0.f;

    // ---- stage x transposed: sXT[f][s], bf16 hi/lo, shuffle-packed pairs ----
    {
        int s = t & 63;
        int fg = t >> 6;
        const float* xr = A + (size_t)s * 64 + fg * 16;
        bool evenS = (s & 1) == 0;
        int s0 = s & ~1;
#pragma unroll
        for (int q = 0; q < 4; q++) {
            float4 v = *(const float4*)(xr + q * 4);
            float vv[4] = {v.x, v.y, v.z, v.w};
#pragma unroll
            for (int e = 0; e < 4; e++) {
                int f = fg * 16 + q * 4 + e;
                __nv_bfloat16 hb = __float2bfloat16(vv[e]);
                __nv_bfloat16 lb = __float2bfloat16(vv[e] - __bfloat162float(hb));
                uint32_t u = (uint32_t)*(uint16_t*)&hb | ((uint32_t)*(uint16_t*)&lb << 16);
                uint32_t pu = __shfl_xor_sync(0xffffffffu, u, 1);
                if (evenS) {
                    uint32_t wh = (u & 0xffffu) | ((pu & 0xffffu) << 16);
                    uint32_t wl = (u >> 16) | (pu & 0xffff0000u);
                    *(uint32_t*)&sXTh[f * XTS + s0] = wh;
                    *(uint32_t*)&sXTl[f * XTS + s0] = wl;
                }
            }
        }
    }
    __syncthreads();
    atomicAdd(&sdeg[e_ed], e_w);
    atomicAdd(&sdeg2[e_es], e_w);
    __syncthreads();
    if (t < NN) {
        sdinv[t] = rsqrtf(sdeg[t] + 1.0f);
        float d2 = sdeg2[t];
        sdv2[t] = (d2 > 0.f) ? rsqrtf(fmaxf(d2, 1e-30f)) : 0.f;
    }
    __syncthreads();
    atomicAdd(&Nf[e_ed * 64 + e_es], sdinv[e_es] * e_w * sdinv[e_ed]);
    if (t < NN) atomicAdd(&Nf[t * 65], sdinv[t] * sdinv[t]);
    __syncthreads();

    // ---- convert N (f32) -> Nb (bf16 split), aliased region: read-all, sync, write ----
    {
        float tmp[16];
#pragma unroll
        for (int j = 0; j < 16; j++) tmp[j] = Nf[t + j * 256];
        __syncthreads();
#pragma unroll
        for (int j = 0; j < 16; j++) {
            int i = t + j * 256;
            int row = i >> 6, col = i & 63;
            __nv_bfloat16 hb = __float2bfloat16(tmp[j]);
            sNbh[row * TST + col] = hb;
            sNbl[row * TST + col] = __float2bfloat16(tmp[j] - __bfloat162float(hb));
        }
    }
    __syncthreads();

    // ---- GEMM1: Nx = N @ x  (M=64 n, N=64 f, K=64 s) ----
    int warpM1 = warp >> 2, warpN1 = warp & 3;   // 2 x 4, warp tile 32n x 16f
    float acc1[2][2][4];
#pragma unroll
    for (int mt = 0; mt < 2; mt++)
#pragma unroll
        for (int nt = 0; nt < 2; nt++)
#pragma unroll
            for (int j = 0; j < 4; j++) acc1[mt][nt][j] = 0.f;
#pragma unroll
    for (int ks = 0; ks < 4; ks++) {
        int kb = ks * 16 + (lane & 3) * 2;
#pragma unroll
        for (int mt = 0; mt < 2; mt++) {
            int r = warpM1 * 32 + mt * 16 + (lane >> 2);
            uint32_t ah[4], al[4];
            ah[0] = *(const uint32_t*)&sNbh[r * TST + kb];
            ah[1] = *(const uint32_t*)&sNbh[(r + 8) * TST + kb];
            ah[2] = *(const uint32_t*)&sNbh[r * TST + kb + 8];
            ah[3] = *(const uint32_t*)&sNbh[(r + 8) * TST + kb + 8];
            al[0] = *(const uint32_t*)&sNbl[r * TST + kb];
            al[1] = *(const uint32_t*)&sNbl[(r + 8) * TST + kb];
            al[2] = *(const uint32_t*)&sNbl[r * TST + kb + 8];
            al[3] = *(const uint32_t*)&sNbl[(r + 8) * TST + kb + 8];
#pragma unroll
            for (int nt = 0; nt < 2; nt++) {
                int f = warpN1 * 16 + nt * 8 + (lane >> 2);
                uint32_t bh[2], bl[2];
                bh[0] = *(const uint32_t*)&sXTh[f * XTS + kb];
                bh[1] = *(const uint32_t*)&sXTh[f * XTS + kb + 8];
                bl[0] = *(const uint32_t*)&sXTl[f * XTS + kb];
                bl[1] = *(const uint32_t*)&sXTl[f * XTS + kb + 8];
                mma_bf16(acc1[mt][nt], ah, bh);
                mma_bf16(acc1[mt][nt], ah, bl);
                mma_bf16(acc1[mt][nt], al, bh);
            }
        }
    }
    __syncthreads();   // xT + Nb reads done; Nx may overwrite xT

    // ---- store Nx (bf16 split) [n][f] ----
#pragma unroll
    for (int mt = 0; mt < 2; mt++) {
        int n0 = warpM1 * 32 + mt * 16 + (lane >> 2);
#pragma unroll
        for (int nt = 0; nt < 2; nt++) {
            int f0 = warpN1 * 16 + nt * 8 + (lane & 3) * 2;
            uint32_t hA, lA, hB, lB;
            cvt_split2(acc1[mt][nt][0], acc1[mt][nt][1], hA, lA);
            cvt_split2(acc1[mt][nt][2], acc1[mt][nt][3], hB, lB);
            *(uint32_t*)&sNxh[n0 * TST + f0]       = hA;
            *(uint32_t*)&sNxl[n0 * TST + f0]       = lA;
            *(uint32_t*)&sNxh[(n0 + 8) * TST + f0] = hB;
            *(uint32_t*)&sNxl[(n0 + 8) * TST + f0] = lB;
        }
    }

    // ---- GEMM2: h = Nx @ Wg  (M=64 n, N=128 c, K=64 f); mt-split for low regs ----
    int warpM = warp >> 2, warpN = warp & 3;   // 2 x 4, warp tile 32n x 32c
    float acc2[2][4][4];
#pragma unroll
    for (int mt = 0; mt < 2; mt++)
#pragma unroll
        for (int nt = 0; nt < 4; nt++)
#pragma unroll
            for (int j = 0; j < 4; j++) acc2[mt][nt][j] = 0.f;

    int lbr = t >> 1, lbc = (t & 1) * 16;
    for (int kc = 0; kc < 64; kc += 32) {
        {
            const __nv_bfloat16* bh = d_wth + (size_t)lbr * 64 + kc + lbc;
            const __nv_bfloat16* bl = d_wtl + (size_t)lbr * 64 + kc + lbc;
            *(uint4*)&sWh[lbr * 40 + lbc]     = *(const uint4*)bh;
            *(uint4*)&sWh[lbr * 40 + lbc + 8] = *(const uint4*)(bh + 8);
            *(uint4*)&sWl[lbr * 40 + lbc]     = *(const uint4*)bl;
            *(uint4*)&sWl[lbr * 40 + lbc + 8] = *(const uint4*)(bl + 8);
        }
        __syncthreads();   // also orders Nx stores before first use
#pragma unroll
        for (int ks = 0; ks < 32; ks += 16) {
            int kb = ks + (lane & 3) * 2;
            int kf = kc + kb;
#pragma unroll
            for (int mt = 0; mt < 2; mt++) {
                int r = warpM * 32 + mt * 16 + (lane >> 2);
                uint32_t ah[4], al[4];
                ah[0] = *(const uint32_t*)&sNxh[r * TST + kf];
                ah[1] = *(const uint32_t*)&sNxh[(r + 8) * TST + kf];
                ah[2] = *(const uint32_t*)&sNxh[r * TST + kf + 8];
                ah[3] = *(const uint32_t*)&sNxh[(r + 8) * TST + kf + 8];
                al[0] = *(const uint32_t*)&sNxl[r * TST + kf];
                al[1] = *(const uint32_t*)&sNxl[(r + 8) * TST + kf];
                al[2] = *(const uint32_t*)&sNxl[r * TST + kf + 8];
                al[3] = *(const uint32_t*)&sNxl[(r + 8) * TST + kf + 8];
#pragma unroll
                for (int nt = 0; nt < 4; nt++) {
                    int rB = warpN * 32 + nt * 8 + (lane >> 2);
                    uint32_t bh[2], bl[2];
                    bh[0] = *(const uint32_t*)&sWh[rB * 40 + kb];
                    bh[1] = *(const uint32_t*)&sWh[rB * 40 + kb + 8];
                    bl[0] = *(const uint32_t*)&sWl[rB * 40 + kb];
                    bl[1] = *(const uint32_t*)&sWl[rB * 40 + kb + 8];
                    mma_bf16(acc2[mt][nt], ah, bh);
                    mma_bf16(acc2[mt][nt], ah, bl);
                    mma_bf16(acc2[mt][nt], al, bh);
                }
            }
        }
        __syncthreads();
    }

    // ---- g_emb partials + h epilogue -> smem ----
#pragma unroll
    for (int nt = 0; nt < 4; nt++) {
        float v0 = acc2[0][nt][0] + acc2[0][nt][2] + acc2[1][nt][0] + acc2[1][nt][2];
        float v1 = acc2[0][nt][1] + acc2[0][nt][3] + acc2[1][nt][1] + acc2[1][nt][3];
#pragma unroll
        for (int off = 4; off <= 16; off <<= 1) {
            v0 += __shfl_xor_sync(0xffffffffu, v0, off);
            v1 += __shfl_xor_sync(0xffffffffu, v1, off);
        }
        if ((lane >> 2) == 0) {
            int c0 = warpN * 32 + nt * 8 + (lane & 3) * 2;
            atomicAdd(&sgpart[c0], v0);
            atomicAdd(&sgpart[c0 + 1], v1);
        }
    }
#pragma unroll
    for (int mt = 0; mt < 2; mt++) {
        int n0 = warpM * 32 + mt * 16 + (lane >> 2);
#pragma unroll
        for (int nt = 0; nt < 4; nt++) {
            int c0 = warpN * 32 + nt * 8 + (lane & 3) * 2;
            float b0 = sbias[c0], b1 = sbias[c0 + 1];
            uint32_t hA, lA, hB, lB;
            cvt_split2(acc2[mt][nt][0] + b0, acc2[mt][nt][1] + b1, hA, lA);
            cvt_split2(acc2[mt][nt][2] + b0, acc2[mt][nt][3] + b1, hB, lB);
            *(uint32_t*)&shh[n0 * HST + c0]       = hA;
            *(uint32_t*)&shl[n0 * HST + c0]       = lA;
            *(uint32_t*)&shh[(n0 + 8) * HST + c0] = hB;
            *(uint32_t*)&shl[(n0 + 8) * HST + c0] = lB;
        }
    }
    __syncthreads();

    if (t < DD)
        d_gembs[(size_t)g * 128 + t] = 0.5f * (sgpart[t] + 64.f * sbias[t]);

    // ---- a1 head across ALL 8 warps: warp = (row-quad = warp&3, nt-half = warp>>2) ----
    {
        int nt = warp >> 2;             // 0 or 1: channel half of Wf1 (8 cols each)
        int rowW = (warp & 3) * 16;
        int r = lane >> 2, kb2 = (lane & 3) * 2;
        float a16[4] = {0.f, 0.f, 0.f, 0.f};
        const __nv_bfloat16* Bh = d_wth + 237568;
        const __nv_bfloat16* Bl = d_wtl + 237568;
        int n = nt * 8 + r;
#pragma unroll
        for (int ks = 0; ks < 8; ks++) {
            int k0 = ks * 16 + kb2;
            uint32_t ah[4], al[4];
            ah[0] = *(const uint32_t*)&shh[(rowW + r) * HST + k0];
            ah[1] = *(const uint32_t*)&shh[(rowW + r + 8) * HST + k0];
            ah[2] = *(const uint32_t*)&shh[(rowW + r) * HST + k0 + 8];
            ah[3] = *(const uint32_t*)&shh[(rowW + r + 8) * HST + k0 + 8];
            al[0] = *(const uint32_t*)&shl[(rowW + r) * HST + k0];
            al[1] = *(const uint32_t*)&shl[(rowW + r + 8) * HST + k0];
            al[2] = *(const uint32_t*)&shl[(rowW + r) * HST + k0 + 8];
            al[3] = *(const uint32_t*)&shl[(rowW + r + 8) * HST + k0 + 8];
            uint32_t bh[2], bl[2];
            bh[0] = *(const uint32_t*)(Bh + n * 128 + k0);
            bh[1] = *(const uint32_t*)(Bh + n * 128 + k0 + 8);
            bl[0] = *(const uint32_t*)(Bl + n * 128 + k0);
            bl[1] = *(const uint32_t*)(Bl + n * 128 + k0 + 8);
            mma_bf16(a16, ah, bh);
            mma_bf16(a16, ah, bl);
            mma_bf16(a16, al, bh);
        }
        // partial logits over this warp's 2 channels (c0, c0+1)
        int c0 = nt * 8 + (lane & 3) * 2;
        float b0 = bf1[c0], b1 = bf1[c0 + 1];
        float w00 = Wf2[c0 * 2], w01 = Wf2[c0 * 2 + 1];
        float w10 = Wf2[c0 * 2 + 2], w11 = Wf2[c0 * 2 + 3];
        float t0 = tanhf(a16[0] + b0), t1 = tanhf(a16[1] + b1);
        float t2 = tanhf(a16[2] + b0), t3 = tanhf(a16[3] + b1);
        float l0a = fmaf(t0, w00, t1 * w10), l1a = fmaf(t0, w01, t1 * w11);
        float l0b = fmaf(t2, w00, t3 * w10), l1b = fmaf(t2, w01, t3 * w11);
#pragma unroll
        for (int off = 1; off <= 2; off <<= 1) {
            l0a += __shfl_xor_sync(0xffffffffu, l0a, off);
            l1a += __shfl_xor_sync(0xffffffffu, l1a, off);
            l0b += __shfl_xor_sync(0xffffffffu, l0b, off);
            l1b += __shfl_xor_sync(0xffffffffu, l1b, off);
        }
        if ((lane & 3) == 0) {
            sLog[nt][rowW + r][0] = l0a;
            sLog[nt][rowW + r][1] = l1a;
            sLog[nt][rowW + r + 8][0] = l0b;
            sLog[nt][rowW + r + 8][1] = l1b;
        }
    }
    __syncthreads();
    if (t < NN) {
        float l0 = sLog[0][t][0] + sLog[1][t][0] + bf2[0];
        float l1 = sLog[0][t][1] + sLog[1][t][1] + bf2[1];
        float m = fmaxf(l0, l1);
        float e0 = expf(l0 - m), e1 = expf(l1 - m);
        float inv = 1.f / (e0 + e1);
        sS[t * 2] = e0 * inv;
        sS[t * 2 + 1] = e1 * inv;
    }
    __syncthreads();

    // ---- Laplacian penalty ----
    {
        float p[4] = {0, 0, 0, 0};
        if (t < NN) {
            float s0 = sS[t * 2], s1 = sS[t * 2 + 1];
            p[0] = s0 * s0; p[1] = s0 * s1; p[2] = s1 * s0; p[3] = s1 * s1;
        }
        {
            float lw = -sdv2[e_es] * e_w * sdv2[e_ed];
            float q0 = sS[e_es * 2], q1 = sS[e_es * 2 + 1];
            float r0 = sS[e_ed * 2], r1 = sS[e_ed * 2 + 1];
            p[0] = fmaf(lw, q0 * r0, p[0]);
            p[1] = fmaf(lw, q0 * r1, p[1]);
            p[2] = fmaf(lw, q1 * r0, p[2]);
            p[3] = fmaf(lw, q1 * r1, p[3]);
        }
#pragma unroll
        for (int off = 16; off; off >>= 1)
#pragma unroll
            for (int j = 0; j < 4; j++)
                p[j] += __shfl_down_sync(0xffffffffu, p[j], off);
        if (lane == 0) {
#pragma unroll
            for (int j = 0; j < 4; j++) atomicAdd(&sped[j], p[j]);
        }
    }
    __syncthreads();
    if (t == 0) {
        float A00 = sped[0], A01 = sped[1], A10 = sped[2], A11 = sped[3];
        float r0 = fmaxf(fabsf(A00) + fabsf(A01), 1e-12f);
        float r1 = fmaxf(fabsf(A10) + fabsf(A11), 1e-12f);
        float dd0 = A00 / r0 - 1.f, dd1 = A11 / r1 - 1.f;
        atomicAdd(&d_sums[0], 0.5f * (dd0 * dd0 + dd1 * dd1));
    }
}

// ---------------- dual-output mma.sync GEMM: C = act(A @ W + b) ----------------
__global__ void __launch_bounds__(256) k_mma(
    int selA, int K, int nx0,
    int wtoff0, int wtoff1,
    const float* __restrict__ b0v, const float* __restrict__ b1v,
    int selC0, int selC1, int Cs, int act0, int act1)
{
    __shared__ __nv_bfloat16 sAh[128][40];
    __shared__ __nv_bfloat16 sAl[128][40];
    __shared__ __nv_bfloat16 sBh[128][40];
    __shared__ __nv_bfloat16 sBl[128][40];
    __shared__ float sbias[128];

    int t = threadIdx.x;
    const float* A = (selA == 1) ? d_agg1 : (selA == 2) ? d_agg2 : d_zc;
    int bx = blockIdx.x;
    int hsel = bx >= nx0;
    int colBase = (bx - (hsel ? nx0 : 0)) * 128;
    int wtoff = hsel ? wtoff1 : wtoff0;
    const float* bias = hsel ? b1v : b0v;
    int act = hsel ? act1 : act0;
    int selC = hsel ? selC1 : selC0;
    float* C = (selC == 1) ? d_h : (selC == 2) ? d_mu
             : (selC == 3) ? d_ls : (selC == 4) ? d_zl1 : d_zl2;
    int rowBase = blockIdx.y * 128;
    if (t < 128) sbias[t] = bias[colBase + t];

    int lane = t & 31, warp = t >> 5;
    int warpM = warp >> 2, warpN = warp & 3;

    float acc[4][4][4];
#pragma unroll
    for (int mt = 0; mt < 4; mt++)
#pragma unroll
        for (int nt = 0; nt < 4; nt++)
#pragma unroll
            for (int j = 0; j < 4; j++) acc[mt][nt][j] = 0.f;

    int ldr = t >> 1, ldc = (t & 1) * 16;

    for (int kc = 0; kc < K; kc += 32) {
        const float* Ar = A + (size_t)(rowBase + ldr) * K + kc + ldc;
#pragma unroll
        for (int j = 0; j < 4; j++) {
            float4 v = *(const float4*)(Ar + j * 4);
            uint32_t h0, l0, h1, l1;
            cvt_split2(v.x, v.y, h0, l0);
            cvt_split2(v.z, v.w, h1, l1);
            *(uint32_t*)&sAh[ldr][ldc + j * 4]     = h0;
            *(uint32_t*)&sAh[ldr][ldc + j * 4 + 2] = h1;
            *(uint32_t*)&sAl[ldr][ldc + j * 4]     = l0;
            *(uint32_t*)&sAl[ldr][ldc + j * 4 + 2] = l1;
        }
        {
            const __nv_bfloat16* bh = d_wth + wtoff + (size_t)(colBase + ldr) * K + kc + ldc;
            const __nv_bfloat16* bl = d_wtl + wtoff + (size_t)(colBase + ldr) * K + kc + ldc;
            *(uint4*)&sBh[ldr][ldc]     = *(const uint4*)bh;
            *(uint4*)&sBh[ldr][ldc + 8] = *(const uint4*)(bh + 8);
            *(uint4*)&sBl[ldr][ldc]     = *(const uint4*)bl;
            *(uint4*)&sBl[ldr][ldc + 8] = *(const uint4*)(bl + 8);
        }
        __syncthreads();
#pragma unroll
        for (int ks = 0; ks < 32; ks += 16) {
            int kb = ks + (lane & 3) * 2;
            int ar = warpM * 64 + (lane >> 2);
            uint32_t ah[4][4], al[4][4];
#pragma unroll
            for (int mt = 0; mt < 4; mt++) {
                int r = ar + mt * 16;
                ah[mt][0] = *(const uint32_t*)&sAh[r][kb];
                ah[mt][1] = *(const uint32_t*)&sAh[r + 8][kb];
                ah[mt][2] = *(const uint32_t*)&sAh[r][kb + 8];
                ah[mt][3] = *(const uint32_t*)&sAh[r + 8][kb + 8];
                al[mt][0] = *(const uint32_t*)&sAl[r][kb];
                al[mt][1] = *(const uint32_t*)&sAl[r + 8][kb];
                al[mt][2] = *(const uint32_t*)&sAl[r][kb + 8];
                al[mt][3] = *(const uint32_t*)&sAl[r + 8][kb + 8];
            }
            uint32_t bhf[4][2], blf[4][2];
#pragma unroll
            for (int nt = 0; nt < 4; nt++) {
                int r = warpN * 32 + nt * 8 + (lane >> 2);
                bhf[nt][0] = *(const uint32_t*)&sBh[r][kb];
                bhf[nt][1] = *(const uint32_t*)&sBh[r][kb + 8];
                blf[nt][0] = *(const uint32_t*)&sBl[r][kb];
                blf[nt][1] = *(const uint32_t*)&sBl[r][kb + 8];
            }
#pragma unroll
            for (int mt = 0; mt < 4; mt++)
#pragma unroll
                for (int nt = 0; nt < 4; nt++) {
                    mma_bf16(acc[mt][nt], ah[mt], bhf[nt]);
                    mma_bf16(acc[mt][nt], ah[mt], blf[nt]);
                    mma_bf16(acc[mt][nt], al[mt], bhf[nt]);
                }
        }
        __syncthreads();
    }

#pragma unroll
    for (int mt = 0; mt < 4; mt++) {
        int r0 = rowBase + warpM * 64 + mt * 16 + (lane >> 2);
#pragma unroll
        for (int nt = 0; nt < 4; nt++) {
            int cl = warpN * 32 + nt * 8 + (lane & 3) * 2;
            float b0 = sbias[cl], b1 = sbias[cl + 1];
            float2 v0, v1;
            v0.x = acc[mt][nt][0] + b0; v0.y = acc[mt][nt][1] + b1;
            v1.x = acc[mt][nt][2] + b0; v1.y = acc[mt][nt][3] + b1;
            if (act == 1) {
                v0.x = fmaxf(v0.x, 0.f); v0.y = fmaxf(v0.y, 0.f);
                v1.x = fmaxf(v1.x, 0.f); v1.y = fmaxf(v1.y, 0.f);
            } else if (act == 2) {
                v0.x = fminf(v0.x, 10.f); v0.y = fminf(v0.y, 10.f);
                v1.x = fminf(v1.x, 10.f); v1.y = fminf(v1.y, 10.f);
            }
            *(float2*)&C[(size_t)r0 * Cs + colBase + cl] = v0;
            *(float2*)&C[(size_t)(r0 + 8) * Cs + colBase + cl] = v1;
        }
    }
}

// ---------------- scatter (warp/edge), float4 vector atomics ----------------
__global__ void __launch_bounds__(256) k_scatter(const int* __restrict__ pe, int sel) {
    int tid = blockIdx.x * 256 + threadIdx.x;
    int gw = tid >> 5, lane = tid & 31;
    int a = pe[gw], b = pe[EPN + gw];
    float norm = d_deg[a] * d_deg[b];
    if (sel == 0) {
        const float4* X = (const float4*)(d_gembs + (size_t)a * DD);
        float4* Ag = (float4*)(d_agg1 + (size_t)b * DD);
        float4 v = X[lane];
        v.x *= norm; v.y *= norm; v.z *= norm; v.w *= norm;
        atomicAdd(&Ag[lane], v);
        if (tid < G * DD / 4) {
            float di = d_deg[tid >> 5];
            float d2 = di * di;
            float4 s = ((const float4*)d_gembs)[tid];
            s.x *= d2; s.y *= d2; s.z *= d2; s.w *= d2;
            atomicAdd(&((float4*)d_agg1)[tid], s);
        }
    } else {
        const float4* X = (const float4*)(d_h + (size_t)a * 256);
        float4* Ag = (float4*)(d_agg2 + (size_t)b * 256);
#pragma unroll
        for (int q = 0; q < 2; q++) {
            float4 v = X[lane + 32 * q];
            v.x *= norm; v.y *= norm; v.z *= norm; v.w *= norm;
            atomicAdd(&Ag[lane + 32 * q], v);
        }
        if (tid < G * 256 / 4) {
            float di = d_deg[tid >> 6];
            float d2 = di * di;
            float4 s = ((const float4*)d_h)[tid];
            s.x *= d2; s.y *= d2; s.z *= d2; s.w *= d2;
            atomicAdd(&((float4*)d_agg2)[tid], s);
        }
    }
}

// ---------------- z, zc, KL ----------------
__global__ void __launch_bounds__(256) k_z(const float* __restrict__ eps_,
                                           const float* __restrict__ emb) {
    int i = blockIdx.x * 256 + threadIdx.x;
    float m = d_mu[i], l = d_ls[i];
    int n = i >> 7, d = i & 127;
    float z = m + eps_[i] * expf(l);
    d_zc[(size_t)n * 256 + d] = emb[i];
    d_zc[(size_t)n * 256 + 128 + d] = z;
    float klt = 1.f + 2.f * l - m * m - expf(2.f * l);
    for (int off = 16; off; off >>= 1) klt += __shfl_down_sync(0xffffffffu, klt, off);
    __shared__ float sw[8];
    if ((threadIdx.x & 31) == 0) sw[threadIdx.x >> 5] = klt;
    __syncthreads();
    if (threadIdx.x == 0) {
        float s = 0;
        for (int j = 0; j < 8; j++) s += sw[j];
        atomicAdd(&d_sums[3], s);
    }
}

// ---------------- edge predictions + log sums ----------------
__global__ void __launch_bounds__(256) k_pred(const int* __restrict__ pe,
                                              const int* __restrict__ ne,
                                              float* __restrict__ out) {
    int gw = (blockIdx.x * 256 + threadIdx.x) >> 5;
    int lane = threadIdx.x & 31;
    int wib = threadIdx.x >> 5;
    bool isneg = gw >= EPN;
    int i = isneg ? gw - EPN : gw;
    const int* e = isneg ? ne : pe;
    int a = e[i], b = e[EPN + i];
    const float4* ra = (const float4*)(d_zl1 + (size_t)a * 256);
    const float4* rb = (const float4*)(d_zl2 + (size_t)b * 256);
    float s = 0.f;
#pragma unroll
    for (int q = 0; q < 2; q++) {
        float4 u = ra[lane + 32 * q], v = rb[lane + 32 * q];
        s += u.x * v.x + u.y * v.y + u.z * v.z + u.w * v.w;
    }
    for (int off = 16; off; off >>= 1) s += __shfl_down_sync(0xffffffffu, s, off);
    __shared__ float sl[8];
    if (lane == 0) {
        float p = 1.f / (1.f + expf(-s));
        out[2 + gw] = p;
        sl[wib] = isneg ? logf(1.f - p + 1e-15f) : logf(p + 1e-15f);
    }
    __syncthreads();
    if (threadIdx.x == 0) {
        float tt = 0;
        for (int j = 0; j < 8; j++) tt += sl[j];
        atomicAdd(isneg ? &d_sums[2] : &d_sums[1], tt);
    }
}

__global__ void k_final(float* __restrict__ out) {
    float rec = -(d_sums[1] / (float)EPN) - (d_sums[2] / (float)EPN);
    float kl = -0.5f * d_sums[3] / (float)G;
    out[0] = rec + kl / (float)G;
    out[1] = d_sums[0] / (float)G;
}

// ---------------- launch ----------------
extern "C" void kernel_launch(void* const* d_in, const int* in_sizes, int n_in,
                              void* d_out, int out_size) {
    const float* x   = (const float*)d_in[0];
    const int*   ei  = (const int*)d_in[1];
    const float* ew  = (const float*)d_in[2];
    const int*   pe  = (const int*)d_in[3];
    const int*   ne  = (const int*)d_in[4];
    const float* eps_= (const float*)d_in[5];
    const float* Wg  = (const float*)d_in[6];
    const float* bg  = (const float*)d_in[7];
    const float* Wf1 = (const float*)d_in[8];
    const float* bf1 = (const float*)d_in[9];
    const float* Wf2 = (const float*)d_in[10];
    const float* bf2 = (const float*)d_in[11];
    const float* Wc1 = (const float*)d_in[12];
    const float* bc1 = (const float*)d_in[13];
    const float* Wmu = (const float*)d_in[14];
    const float* bmu = (const float*)d_in[15];
    const float* Wls = (const float*)d_in[16];
    const float* bls = (const float*)d_in[17];
    const float* emb = (const float*)d_in[18];
    const float* Wl1 = (const float*)d_in[19];
    const float* bl1 = (const float*)d_in[20];
    const float* Wl2 = (const float*)d_in[21];
    const float* bl2 = (const float*)d_in[22];
    float* out = (float*)d_out;

    const int dyn_xw = 38912;   // 4 CTAs/SM (with statics ~3.5KB + 1KB reserved)
    cudaFuncSetAttribute(k_xwagg, cudaFuncAttributeMaxDynamicSharedMemorySize, dyn_xw);

    k_zero<<<1024, 256>>>(pe);
    k_prepw<<<234, 1024>>>(Wg, Wc1, Wmu, Wls, Wl1, Wl2, Wf1);
    k_deg<<<EPN / 256, 256>>>(pe);
    k_xwagg<<<G, 256, dyn_xw>>>(x, ei, ew, bg, bf1, Wf2, bf2);
    k_dinv<<<G / 256, 256>>>();
    k_scatter<<<EPN * 32 / 256, 256>>>(pe, 0);
    // h = relu(agg1 @ Wc1 + bc1)   [4096x128]@[128x256]
    k_mma<<<dim3(2, 32), 256>>>(1, 128, 2, 8192, 8192, bc1, bc1, 1, 1, 256, 1, 1);
    k_scatter<<<EPN * 32 / 256, 256>>>(pe, 1);
    // mu | ls   [4096x256]@[256x128] x2 in one launch
    k_mma<<<dim3(2, 32), 256>>>(2, 256, 1, 40960, 73728, bmu, bls, 2, 3, 128, 0, 2);
    k_z<<<G * DD / 256, 256>>>(eps_, emb);
    // zl1 | zl2   [4096x256]@[256x256] x2 in one launch
    k_mma<<<dim3(4, 32), 256>>>(3, 256, 2, 106496, 172032, bl1, bl2, 4, 5, 256, 0, 0);
    k_pred<<<2 * EPN * 32 / 256, 256>>>(pe, ne, out);
    k_final<<<1, 1>>>(out);
}

// round 17
// speedup vs baseline: 1.0731x; 1.0731x over previous
#include <cuda_runtime.h>
#include <cuda_bf16.h>
#include <math.h>
#include <stdint.h>

#define G   4096
#define NN  64
#define EE  256
#define FF  64
#define DD  128
#define EPN 32768

// ---------------- device scratch (static, no allocations) ----------------
__device__ float d_gembs[G * DD];
__device__ float d_deg[G];
__device__ float d_agg1[G * DD];
__device__ float d_h[G * 256];
__device__ float d_agg2[G * 256];
__device__ float d_mu[G * DD];
__device__ float d_ls[G * DD];
__device__ float d_zc[G * 256];
__device__ float d_zl1[G * 256];
__device__ float d_zl2[G * 256];
__device__ float d_sums[8];   // 0:pen 1:plog 2:nlog 3:kl
// transposed bf16 hi/lo weights [N][K]: Wg[0,8192) Wc1[8192,40960) Wmu[40960,73728)
// Wls[73728,106496) Wl1[106496,172032) Wl2[172032,237568) Wf1[237568,239616)
__device__ __nv_bfloat16 d_wth[239616];
__device__ __nv_bfloat16 d_wtl[239616];
// Wg B-fragments, lane-ordered: [hl][ks(4)][ntile(16)][lane(32)][2 words]
__device__ uint32_t d_wgfrag[8192];

// ---------------- helpers ----------------
__device__ __forceinline__ void mma_bf16(float* c, const uint32_t* a, const uint32_t* b) {
    asm volatile("mma.sync.aligned.m16n8k16.row.col.f32.bf16.bf16.f32 "
        "{%0,%1,%2,%3}, {%4,%5,%6,%7}, {%8,%9}, {%0,%1,%2,%3};"
        : "+f"(c[0]), "+f"(c[1]), "+f"(c[2]), "+f"(c[3])
        : "r"(a[0]), "r"(a[1]), "r"(a[2]), "r"(a[3]), "r"(b[0]), "r"(b[1]));
}
__device__ __forceinline__ void cvt_split2(float x, float y, uint32_t& hi, uint32_t& lo) {
    __nv_bfloat162 h = __floats2bfloat162_rn(x, y);
    float rx = x - __bfloat162float(h.x);
    float ry = y - __bfloat162float(h.y);
    __nv_bfloat162 l = __floats2bfloat162_rn(rx, ry);
    hi = *(uint32_t*)&h;
    lo = *(uint32_t*)&l;
}

// ---------------- zero scratch accumulators + graph-level degree ----------------
__global__ void k_zero(const int* __restrict__ pe) {
    int i = blockIdx.x * blockDim.x + threadIdx.x;
    int stride = gridDim.x * blockDim.x;
    for (int j = i; j < G * 256; j += stride) d_agg2[j] = 0.f;
    for (int j = i; j < G * DD; j += stride) d_agg1[j] = 0.f;
    for (int j = i; j < G; j += stride) d_deg[j] = 0.f;
    if (i < 8) d_sums[i] = 0.f;
}
__global__ void k_deg(const int* __restrict__ pe) {
    int i = blockIdx.x * blockDim.x + threadIdx.x;
    if (i < EPN) atomicAdd(&d_deg[pe[EPN + i]], 1.0f);
}
__global__ void k_dinv() {
    int i = blockIdx.x * blockDim.x + threadIdx.x;
    if (i < G) d_deg[i] = rsqrtf(d_deg[i] + 1.0f);
}

// ---------------- weight transpose + bf16 hi/lo split ----------------
__global__ void k_prepw(const float* __restrict__ W0, const float* __restrict__ W1,
                        const float* __restrict__ W2, const float* __restrict__ W3,
                        const float* __restrict__ W4, const float* __restrict__ W5,
                        const float* __restrict__ W6) {
    const float* Ws[7] = {W0, W1, W2, W3, W4, W5, W6};
    const int Ks[7] = {64, 128, 256, 256, 256, 256, 128};
    const int Ns[7] = {128, 256, 128, 128, 256, 256, 16};
    const int offs[8] = {0, 8192, 40960, 73728, 106496, 172032, 237568, 239616};
    int i = blockIdx.x * blockDim.x + threadIdx.x;
    if (i >= 239616) return;
    int s = 0;
    while (i >= offs[s + 1]) s++;
    int local = i - offs[s];
    int K = Ks[s], N = Ns[s];
    int n = local / K, k = local - n * K;
    float v = Ws[s][k * N + n];
    __nv_bfloat16 h = __float2bfloat16(v);
    d_wth[i] = h;
    d_wtl[i] = __float2bfloat16(v - __bfloat162float(h));
}

// ---------------- pack Wg into B-fragment lane order (after k_prepw) ----------------
__global__ void k_prepfrag() {
    int i = blockIdx.x * blockDim.x + threadIdx.x;   // 0..8191
    if (i >= 8192) return;
    int w = i & 1;
    int lane = (i >> 1) & 31;
    int tile = (i >> 6) & 15;
    int ks = (i >> 10) & 3;
    int hl = i >> 12;
    int n = tile * 8 + (lane >> 2);
    int k = ks * 16 + (lane & 3) * 2 + w * 8;
    const __nv_bfloat16* src = hl ? d_wtl : d_wth;   // Wg at offset 0, [128][64]
    __nv_bfloat16 v0 = src[n * 64 + k];
    __nv_bfloat16 v1 = src[n * 64 + k + 1];
    d_wgfrag[i] = (uint32_t)*(uint16_t*)&v0 | ((uint32_t)*(uint16_t*)&v1 << 16);
}

// ---------------- fully fused per-graph kernel (1 graph / block) ----------------
// Nx = N @ x (HMMA split), then h = Nx @ Wg with B-frags from prepacked GLOBAL
// (L1-resident); g_emb from fragments; 8-warp a1 head. dyn smem 36864 B.
#define XTS 72
#define TST 72
#define HST 136
__global__ void __launch_bounds__(256, 3) k_xwagg(
    const float* __restrict__ x, const int* __restrict__ ei, const float* __restrict__ ew,
    const float* __restrict__ bg, const float* __restrict__ bf1,
    const float* __restrict__ Wf2, const float* __restrict__ bf2)
{
    extern __shared__ char dyn[];
    __nv_bfloat16* sXTh = (__nv_bfloat16*)dyn;          // [64 f][XTS], [0,18432)
    __nv_bfloat16* sXTl = sXTh + 64 * XTS;
    float* Nf = (float*)(dyn + 18432);                  // [64][64] f32 (transient)
    __nv_bfloat16* sNbh = (__nv_bfloat16*)(dyn + 18432);// [64][TST] (aliases Nf), ends 36864
    __nv_bfloat16* sNbl = sNbh + 64 * TST;
    __nv_bfloat16* sNxh = (__nv_bfloat16*)dyn;          // [64 n][TST] (aliases xT)
    __nv_bfloat16* sNxl = sNxh + 64 * TST;
    __nv_bfloat16* shh = (__nv_bfloat16*)dyn;           // [64][HST] h, [0,34816)
    __nv_bfloat16* shl = shh + 64 * HST;

    __shared__ float sdeg[NN], sdinv[NN], sdeg2[NN], sdv2[NN];
    __shared__ float sbias[DD];
    __shared__ float sS[NN * 2];
    __shared__ float sgpart[DD];
    __shared__ float sped[4];
    __shared__ float sLog[2][NN][2];

    int t = threadIdx.x, lane = t & 31, warp = t >> 5;
    int g = blockIdx.x;
    const float* A = x + (size_t)g * NN * FF;

    // ---- phase 0: edges, init ----
    int e_es = ei[(size_t)g * 512 + t];
    int e_ed = ei[(size_t)g * 512 + 256 + t];
    float e_w = ew[(size_t)g * 256 + t];
    if (t < NN) { sdeg[t] = 0.f; sdeg2[t] = 0.f; }
    if (t < DD) { sbias[t] = bg[t]; sgpart[t] = 0.f; }
    if (t < 4) sped[t] = 0.f;
#pragma unroll
    for (int j = 0; j < 16; j++) Nf[t + j * 256] = 0.f;

    // ---- stage x transposed: sXT[f][s], bf16 hi/lo, shuffle-packed pairs ----
    {
        int s = t & 63;
        int fg = t >> 6;
        const float* xr = A + (size_t)s * 64 + fg * 16;
        bool evenS = (s & 1) == 0;
        int s0 = s & ~1;
#pragma unroll
        for (int q = 0; q < 4; q++) {
            float4 v = *(const float4*)(xr + q * 4);
            float vv[4] = {v.x, v.y, v.z, v.w};
#pragma unroll
            for (int e = 0; e < 4; e++) {
                int f = fg * 16 + q * 4 + e;
                __nv_bfloat16 hb = __float2bfloat16(vv[e]);
                __nv_bfloat16 lb = __float2bfloat16(vv[e] - __bfloat162float(hb));
                uint32_t u = (uint32_t)*(uint16_t*)&hb | ((uint32_t)*(uint16_t*)&lb << 16);
                uint32_t pu = __shfl_xor_sync(0xffffffffu, u, 1);
                if (evenS) {
                    uint32_t wh = (u & 0xffffu) | ((pu & 0xffffu) << 16);
                    uint32_t wl = (u >> 16) | (pu & 0xffff0000u);
                    *(uint32_t*)&sXTh[f * XTS + s0] = wh;
                    *(uint32_t*)&sXTl[f * XTS + s0] = wl;
                }
            }
        }
    }
    __syncthreads();
    atomicAdd(&sdeg[e_ed], e_w);
    atomicAdd(&sdeg2[e_es], e_w);
    __syncthreads();
    if (t < NN) {
        sdinv[t] = rsqrtf(sdeg[t] + 1.0f);
        float d2 = sdeg2[t];
        sdv2[t] = (d2 > 0.f) ? rsqrtf(fmaxf(d2, 1e-30f)) : 0.f;
    }
    __syncthreads();
    atomicAdd(&Nf[e_ed * 64 + e_es], sdinv[e_es] * e_w * sdinv[e_ed]);
    if (t < NN) atomicAdd(&Nf[t * 65], sdinv[t] * sdinv[t]);
    __syncthreads();

    // ---- convert N (f32) -> Nb (bf16 split), aliased region ----
    {
        float tmp[16];
#pragma unroll
        for (int j = 0; j < 16; j++) tmp[j] = Nf[t + j * 256];
        __syncthreads();
#pragma unroll
        for (int j = 0; j < 16; j++) {
            int i = t + j * 256;
            int row = i >> 6, col = i & 63;
            __nv_bfloat16 hb = __float2bfloat16(tmp[j]);
            sNbh[row * TST + col] = hb;
            sNbl[row * TST + col] = __float2bfloat16(tmp[j] - __bfloat162float(hb));
        }
    }
    __syncthreads();

    // ---- GEMM1: Nx = N @ x  (M=64 n, N=64 f, K=64 s) ----
    int warpM1 = warp >> 2, warpN1 = warp & 3;
    float acc1[2][2][4];
#pragma unroll
    for (int mt = 0; mt < 2; mt++)
#pragma unroll
        for (int nt = 0; nt < 2; nt++)
#pragma unroll
            for (int j = 0; j < 4; j++) acc1[mt][nt][j] = 0.f;
#pragma unroll
    for (int ks = 0; ks < 4; ks++) {
        int kb = ks * 16 + (lane & 3) * 2;
#pragma unroll
        for (int mt = 0; mt < 2; mt++) {
            int r = warpM1 * 32 + mt * 16 + (lane >> 2);
            uint32_t ah[4], al[4];
            ah[0] = *(const uint32_t*)&sNbh[r * TST + kb];
            ah[1] = *(const uint32_t*)&sNbh[(r + 8) * TST + kb];
            ah[2] = *(const uint32_t*)&sNbh[r * TST + kb + 8];
            ah[3] = *(const uint32_t*)&sNbh[(r + 8) * TST + kb + 8];
            al[0] = *(const uint32_t*)&sNbl[r * TST + kb];
            al[1] = *(const uint32_t*)&sNbl[(r + 8) * TST + kb];
            al[2] = *(const uint32_t*)&sNbl[r * TST + kb + 8];
            al[3] = *(const uint32_t*)&sNbl[(r + 8) * TST + kb + 8];
#pragma unroll
            for (int nt = 0; nt < 2; nt++) {
                int f = warpN1 * 16 + nt * 8 + (lane >> 2);
                uint32_t bh[2], bl[2];
                bh[0] = *(const uint32_t*)&sXTh[f * XTS + kb];
                bh[1] = *(const uint32_t*)&sXTh[f * XTS + kb + 8];
                bl[0] = *(const uint32_t*)&sXTl[f * XTS + kb];
                bl[1] = *(const uint32_t*)&sXTl[f * XTS + kb + 8];
                mma_bf16(acc1[mt][nt], ah, bh);
                mma_bf16(acc1[mt][nt], ah, bl);
                mma_bf16(acc1[mt][nt], al, bh);
            }
        }
    }
    __syncthreads();   // xT + Nb reads done; Nx may overwrite xT

    // ---- store Nx (bf16 split) [n][f] ----
#pragma unroll
    for (int mt = 0; mt < 2; mt++) {
        int n0 = warpM1 * 32 + mt * 16 + (lane >> 2);
#pragma unroll
        for (int nt = 0; nt < 2; nt++) {
            int f0 = warpN1 * 16 + nt * 8 + (lane & 3) * 2;
            uint32_t hA, lA, hB, lB;
            cvt_split2(acc1[mt][nt][0], acc1[mt][nt][1], hA, lA);
            cvt_split2(acc1[mt][nt][2], acc1[mt][nt][3], hB, lB);
            *(uint32_t*)&sNxh[n0 * TST + f0]       = hA;
            *(uint32_t*)&sNxl[n0 * TST + f0]       = lA;
            *(uint32_t*)&sNxh[(n0 + 8) * TST + f0] = hB;
            *(uint32_t*)&sNxl[(n0 + 8) * TST + f0] = lB;
        }
    }
    __syncthreads();

    // ---- GEMM2: h = Nx @ Wg  (M=64 n, N=128 c, K=64 f); B-frags from GLOBAL ----
    int warpM = warp >> 2, warpN = warp & 3;   // 2 x 4, warp tile 32n x 32c
    float acc2[2][4][4];
#pragma unroll
    for (int mt = 0; mt < 2; mt++)
#pragma unroll
        for (int nt = 0; nt < 4; nt++)
#pragma unroll
            for (int j = 0; j < 4; j++) acc2[mt][nt][j] = 0.f;

#pragma unroll
    for (int ks = 0; ks < 4; ks++) {
        int kf = ks * 16 + (lane & 3) * 2;
        uint32_t bhf[4][2], blf[4][2];
#pragma unroll
        for (int nt = 0; nt < 4; nt++) {
            int tile = warpN * 4 + nt;
            uint2 vh = *(const uint2*)&d_wgfrag[((ks * 16 + tile) * 32 + lane) * 2];
            uint2 vl = *(const uint2*)&d_wgfrag[4096 + ((ks * 16 + tile) * 32 + lane) * 2];
            bhf[nt][0] = vh.x; bhf[nt][1] = vh.y;
            blf[nt][0] = vl.x; blf[nt][1] = vl.y;
        }
#pragma unroll
        for (int mt = 0; mt < 2; mt++) {
            int r = warpM * 32 + mt * 16 + (lane >> 2);
            uint32_t ah[4], al[4];
            ah[0] = *(const uint32_t*)&sNxh[r * TST + kf];
            ah[1] = *(const uint32_t*)&sNxh[(r + 8) * TST + kf];
            ah[2] = *(const uint32_t*)&sNxh[r * TST + kf + 8];
            ah[3] = *(const uint32_t*)&sNxh[(r + 8) * TST + kf + 8];
            al[0] = *(const uint32_t*)&sNxl[r * TST + kf];
            al[1] = *(const uint32_t*)&sNxl[(r + 8) * TST + kf];
            al[2] = *(const uint32_t*)&sNxl[r * TST + kf + 8];
            al[3] = *(const uint32_t*)&sNxl[(r + 8) * TST + kf + 8];
#pragma unroll
            for (int nt = 0; nt < 4; nt++) {
                mma_bf16(acc2[mt][nt], ah, bhf[nt]);
                mma_bf16(acc2[mt][nt], ah, blf[nt]);
                mma_bf16(acc2[mt][nt], al, bhf[nt]);
            }
        }
    }
    __syncthreads();   // all Nx reads done before h overwrites region

    // ---- g_emb partials + h epilogue -> smem ----
#pragma unroll
    for (int nt = 0; nt < 4; nt++) {
        float v0 = acc2[0][nt][0] + acc2[0][nt][2] + acc2[1][nt][0] + acc2[1][nt][2];
        float v1 = acc2[0][nt][1] + acc2[0][nt][3] + acc2[1][nt][1] + acc2[1][nt][3];
#pragma unroll
        for (int off = 4; off <= 16; off <<= 1) {
            v0 += __shfl_xor_sync(0xffffffffu, v0, off);
            v1 += __shfl_xor_sync(0xffffffffu, v1, off);
        }
        if ((lane >> 2) == 0) {
            int c0 = warpN * 32 + nt * 8 + (lane & 3) * 2;
            atomicAdd(&sgpart[c0], v0);
            atomicAdd(&sgpart[c0 + 1], v1);
        }
    }
#pragma unroll
    for (int mt = 0; mt < 2; mt++) {
        int n0 = warpM * 32 + mt * 16 + (lane >> 2);
#pragma unroll
        for (int nt = 0; nt < 4; nt++) {
            int c0 = warpN * 32 + nt * 8 + (lane & 3) * 2;
            float b0 = sbias[c0], b1 = sbias[c0 + 1];
            uint32_t hA, lA, hB, lB;
            cvt_split2(acc2[mt][nt][0] + b0, acc2[mt][nt][1] + b1, hA, lA);
            cvt_split2(acc2[mt][nt][2] + b0, acc2[mt][nt][3] + b1, hB, lB);
            *(uint32_t*)&shh[n0 * HST + c0]       = hA;
            *(uint32_t*)&shl[n0 * HST + c0]       = lA;
            *(uint32_t*)&shh[(n0 + 8) * HST + c0] = hB;
            *(uint32_t*)&shl[(n0 + 8) * HST + c0] = lB;
        }
    }
    __syncthreads();

    if (t < DD)
        d_gembs[(size_t)g * 128 + t] = 0.5f * (sgpart[t] + 64.f * sbias[t]);

    // ---- a1 head across 8 warps: warp = (row-quad = warp&3, nt-half = warp>>2) ----
    {
        int nt = warp >> 2;
        int rowW = (warp & 3) * 16;
        int r = lane >> 2, kb2 = (lane & 3) * 2;
        float a16[4] = {0.f, 0.f, 0.f, 0.f};
        const __nv_bfloat16* Bh = d_wth + 237568;
        const __nv_bfloat16* Bl = d_wtl + 237568;
        int n = nt * 8 + r;
#pragma unroll
        for (int ks = 0; ks < 8; ks++) {
            int k0 = ks * 16 + kb2;
            uint32_t ah[4], al[4];
            ah[0] = *(const uint32_t*)&shh[(rowW + r) * HST + k0];
            ah[1] = *(const uint32_t*)&shh[(rowW + r + 8) * HST + k0];
            ah[2] = *(const uint32_t*)&shh[(rowW + r) * HST + k0 + 8];
            ah[3] = *(const uint32_t*)&shh[(rowW + r + 8) * HST + k0 + 8];
            al[0] = *(const uint32_t*)&shl[(rowW + r) * HST + k0];
            al[1] = *(const uint32_t*)&shl[(rowW + r + 8) * HST + k0];
            al[2] = *(const uint32_t*)&shl[(rowW + r) * HST + k0 + 8];
            al[3] = *(const uint32_t*)&shl[(rowW + r + 8) * HST + k0 + 8];
            uint32_t bh[2], bl[2];
            bh[0] = *(const uint32_t*)(Bh + n * 128 + k0);
            bh[1] = *(const uint32_t*)(Bh + n * 128 + k0 + 8);
            bl[0] = *(const uint32_t*)(Bl + n * 128 + k0);
            bl[1] = *(const uint32_t*)(Bl + n * 128 + k0 + 8);
            mma_bf16(a16, ah, bh);
            mma_bf16(a16, ah, bl);
            mma_bf16(a16, al, bh);
        }
        int c0 = nt * 8 + (lane & 3) * 2;
        float b0 = bf1[c0], b1 = bf1[c0 + 1];
        float w00 = Wf2[c0 * 2], w01 = Wf2[c0 * 2 + 1];
        float w10 = Wf2[c0 * 2 + 2], w11 = Wf2[c0 * 2 + 3];
        float t0 = tanhf(a16[0] + b0), t1 = tanhf(a16[1] + b1);
        float t2 = tanhf(a16[2] + b0), t3 = tanhf(a16[3] + b1);
        float l0a = fmaf(t0, w00, t1 * w10), l1a = fmaf(t0, w01, t1 * w11);
        float l0b = fmaf(t2, w00, t3 * w10), l1b = fmaf(t2, w01, t3 * w11);
#pragma unroll
        for (int off = 1; off <= 2; off <<= 1) {
            l0a += __shfl_xor_sync(0xffffffffu, l0a, off);
            l1a += __shfl_xor_sync(0xffffffffu, l1a, off);
            l0b += __shfl_xor_sync(0xffffffffu, l0b, off);
            l1b += __shfl_xor_sync(0xffffffffu, l1b, off);
        }
        if ((lane & 3) == 0) {
            sLog[nt][rowW + r][0] = l0a;
            sLog[nt][rowW + r][1] = l1a;
            sLog[nt][rowW + r + 8][0] = l0b;
            sLog[nt][rowW + r + 8][1] = l1b;
        }
    }
    __syncthreads();
    if (t < NN) {
        float l0 = sLog[0][t][0] + sLog[1][t][0] + bf2[0];
        float l1 = sLog[0][t][1] + sLog[1][t][1] + bf2[1];
        float m = fmaxf(l0, l1);
        float e0 = expf(l0 - m), e1 = expf(l1 - m);
        float inv = 1.f / (e0 + e1);
        sS[t * 2] = e0 * inv;
        sS[t * 2 + 1] = e1 * inv;
    }
    __syncthreads();

    // ---- Laplacian penalty ----
    {
        float p[4] = {0, 0, 0, 0};
        if (t < NN) {
            float s0 = sS[t * 2], s1 = sS[t * 2 + 1];
            p[0] = s0 * s0; p[1] = s0 * s1; p[2] = s1 * s0; p[3] = s1 * s1;
        }
        {
            float lw = -sdv2[e_es] * e_w * sdv2[e_ed];
            float q0 = sS[e_es * 2], q1 = sS[e_es * 2 + 1];
            float r0 = sS[e_ed * 2], r1 = sS[e_ed * 2 + 1];
            p[0] = fmaf(lw, q0 * r0, p[0]);
            p[1] = fmaf(lw, q0 * r1, p[1]);
            p[2] = fmaf(lw, q1 * r0, p[2]);
            p[3] = fmaf(lw, q1 * r1, p[3]);
        }
#pragma unroll
        for (int off = 16; off; off >>= 1)
#pragma unroll
            for (int j = 0; j < 4; j++)
                p[j] += __shfl_down_sync(0xffffffffu, p[j], off);
        if (lane == 0) {
#pragma unroll
            for (int j = 0; j < 4; j++) atomicAdd(&sped[j], p[j]);
        }
    }
    __syncthreads();
    if (t == 0) {
        float A00 = sped[0], A01 = sped[1], A10 = sped[2], A11 = sped[3];
        float r0 = fmaxf(fabsf(A00) + fabsf(A01), 1e-12f);
        float r1 = fmaxf(fabsf(A10) + fabsf(A11), 1e-12f);
        float dd0 = A00 / r0 - 1.f, dd1 = A11 / r1 - 1.f;
        atomicAdd(&d_sums[0], 0.5f * (dd0 * dd0 + dd1 * dd1));
    }
}

// ---------------- dual-output mma.sync GEMM: C = act(A @ W + b) ----------------
__global__ void __launch_bounds__(256) k_mma(
    int selA, int K, int nx0,
    int wtoff0, int wtoff1,
    const float* __restrict__ b0v, const float* __restrict__ b1v,
    int selC0, int selC1, int Cs, int act0, int act1)
{
    __shared__ __nv_bfloat16 sAh[128][40];
    __shared__ __nv_bfloat16 sAl[128][40];
    __shared__ __nv_bfloat16 sBh[128][40];
    __shared__ __nv_bfloat16 sBl[128][40];
    __shared__ float sbias[128];

    int t = threadIdx.x;
    const float* A = (selA == 1) ? d_agg1 : (selA == 2) ? d_agg2 : d_zc;
    int bx = blockIdx.x;
    int hsel = bx >= nx0;
    int colBase = (bx - (hsel ? nx0 : 0)) * 128;
    int wtoff = hsel ? wtoff1 : wtoff0;
    const float* bias = hsel ? b1v : b0v;
    int act = hsel ? act1 : act0;
    int selC = hsel ? selC1 : selC0;
    float* C = (selC == 1) ? d_h : (selC == 2) ? d_mu
             : (selC == 3) ? d_ls : (selC == 4) ? d_zl1 : d_zl2;
    int rowBase = blockIdx.y * 128;
    if (t < 128) sbias[t] = bias[colBase + t];

    int lane = t & 31, warp = t >> 5;
    int warpM = warp >> 2, warpN = warp & 3;

    float acc[4][4][4];
#pragma unroll
    for (int mt = 0; mt < 4; mt++)
#pragma unroll
        for (int nt = 0; nt < 4; nt++)
#pragma unroll
            for (int j = 0; j < 4; j++) acc[mt][nt][j] = 0.f;

    int ldr = t >> 1, ldc = (t & 1) * 16;

    for (int kc = 0; kc < K; kc += 32) {
        const float* Ar = A + (size_t)(rowBase + ldr) * K + kc + ldc;
#pragma unroll
        for (int j = 0; j < 4; j++) {
            float4 v = *(const float4*)(Ar + j * 4);
            uint32_t h0, l0, h1, l1;
            cvt_split2(v.x, v.y, h0, l0);
            cvt_split2(v.z, v.w, h1, l1);
            *(uint32_t*)&sAh[ldr][ldc + j * 4]     = h0;
            *(uint32_t*)&sAh[ldr][ldc + j * 4 + 2] = h1;
            *(uint32_t*)&sAl[ldr][ldc + j * 4]     = l0;
            *(uint32_t*)&sAl[ldr][ldc + j * 4 + 2] = l1;
        }
        {
            const __nv_bfloat16* bh = d_wth + wtoff + (size_t)(colBase + ldr) * K + kc + ldc;
            const __nv_bfloat16* bl = d_wtl + wtoff + (size_t)(colBase + ldr) * K + kc + ldc;
            *(uint4*)&sBh[ldr][ldc]     = *(const uint4*)bh;
            *(uint4*)&sBh[ldr][ldc + 8] = *(const uint4*)(bh + 8);
            *(uint4*)&sBl[ldr][ldc]     = *(const uint4*)bl;
            *(uint4*)&sBl[ldr][ldc + 8] = *(const uint4*)(bl + 8);
        }
        __syncthreads();
#pragma unroll
        for (int ks = 0; ks < 32; ks += 16) {
            int kb = ks + (lane & 3) * 2;
            int ar = warpM * 64 + (lane >> 2);
            uint32_t ah[4][4], al[4][4];
#pragma unroll
            for (int mt = 0; mt < 4; mt++) {
                int r = ar + mt * 16;
                ah[mt][0] = *(const uint32_t*)&sAh[r][kb];
                ah[mt][1] = *(const uint32_t*)&sAh[r + 8][kb];
                ah[mt][2] = *(const uint32_t*)&sAh[r][kb + 8];
                ah[mt][3] = *(const uint32_t*)&sAh[r + 8][kb + 8];
                al[mt][0] = *(const uint32_t*)&sAl[r][kb];
                al[mt][1] = *(const uint32_t*)&sAl[r + 8][kb];
                al[mt][2] = *(const uint32_t*)&sAl[r][kb + 8];
                al[mt][3] = *(const uint32_t*)&sAl[r + 8][kb + 8];
            }
            uint32_t bhf[4][2], blf[4][2];
#pragma unroll
            for (int nt = 0; nt < 4; nt++) {
                int r = warpN * 32 + nt * 8 + (lane >> 2);
                bhf[nt][0] = *(const uint32_t*)&sBh[r][kb];
                bhf[nt][1] = *(const uint32_t*)&sBh[r][kb + 8];
                blf[nt][0] = *(const uint32_t*)&sBl[r][kb];
                blf[nt][1] = *(const uint32_t*)&sBl[r][kb + 8];
            }
#pragma unroll
            for (int mt = 0; mt < 4; mt++)
#pragma unroll
                for (int nt = 0; nt < 4; nt++) {
                    mma_bf16(acc[mt][nt], ah[mt], bhf[nt]);
                    mma_bf16(acc[mt][nt], ah[mt], blf[nt]);
                    mma_bf16(acc[mt][nt], al[mt], bhf[nt]);
                }
        }
        __syncthreads();
    }

#pragma unroll
    for (int mt = 0; mt < 4; mt++) {
        int r0 = rowBase + warpM * 64 + mt * 16 + (lane >> 2);
#pragma unroll
        for (int nt = 0; nt < 4; nt++) {
            int cl = warpN * 32 + nt * 8 + (lane & 3) * 2;
            float b0 = sbias[cl], b1 = sbias[cl + 1];
            float2 v0, v1;
            v0.x = acc[mt][nt][0] + b0; v0.y = acc[mt][nt][1] + b1;
            v1.x = acc[mt][nt][2] + b0; v1.y = acc[mt][nt][3] + b1;
            if (act == 1) {
                v0.x = fmaxf(v0.x, 0.f); v0.y = fmaxf(v0.y, 0.f);
                v1.x = fmaxf(v1.x, 0.f); v1.y = fmaxf(v1.y, 0.f);
            } else if (act == 2) {
                v0.x = fminf(v0.x, 10.f); v0.y = fminf(v0.y, 10.f);
                v1.x = fminf(v1.x, 10.f); v1.y = fminf(v1.y, 10.f);
            }
            *(float2*)&C[(size_t)r0 * Cs + colBase + cl] = v0;
            *(float2*)&C[(size_t)(r0 + 8) * Cs + colBase + cl] = v1;
        }
    }
}

// ---------------- scatter (warp/edge), float4 vector atomics ----------------
__global__ void __launch_bounds__(256) k_scatter(const int* __restrict__ pe, int sel) {
    int tid = blockIdx.x * 256 + threadIdx.x;
    int gw = tid >> 5, lane = tid & 31;
    int a = pe[gw], b = pe[EPN + gw];
    float norm = d_deg[a] * d_deg[b];
    if (sel == 0) {
        const float4* X = (const float4*)(d_gembs + (size_t)a * DD);
        float4* Ag = (float4*)(d_agg1 + (size_t)b * DD);
        float4 v = X[lane];
        v.x *= norm; v.y *= norm; v.z *= norm; v.w *= norm;
        atomicAdd(&Ag[lane], v);
        if (tid < G * DD / 4) {
            float di = d_deg[tid >> 5];
            float d2 = di * di;
            float4 s = ((const float4*)d_gembs)[tid];
            s.x *= d2; s.y *= d2; s.z *= d2; s.w *= d2;
            atomicAdd(&((float4*)d_agg1)[tid], s);
        }
    } else {
        const float4* X = (const float4*)(d_h + (size_t)a * 256);
        float4* Ag = (float4*)(d_agg2 + (size_t)b * 256);
#pragma unroll
        for (int q = 0; q < 2; q++) {
            float4 v = X[lane + 32 * q];
            v.x *= norm; v.y *= norm; v.z *= norm; v.w *= norm;
            atomicAdd(&Ag[lane + 32 * q], v);
        }
        if (tid < G * 256 / 4) {
            float di = d_deg[tid >> 6];
            float d2 = di * di;
            float4 s = ((const float4*)d_h)[tid];
            s.x *= d2; s.y *= d2; s.z *= d2; s.w *= d2;
            atomicAdd(&((float4*)d_agg2)[tid], s);
        }
    }
}

// ---------------- z, zc, KL ----------------
__global__ void __launch_bounds__(256) k_z(const float* __restrict__ eps_,
                                           const float* __restrict__ emb) {
    int i = blockIdx.x * 256 + threadIdx.x;
    float m = d_mu[i], l = d_ls[i];
    int n = i >> 7, d = i & 127;
    float z = m + eps_[i] * expf(l);
    d_zc[(size_t)n * 256 + d] = emb[i];
    d_zc[(size_t)n * 256 + 128 + d] = z;
    float klt = 1.f + 2.f * l - m * m - expf(2.f * l);
    for (int off = 16; off; off >>= 1) klt += __shfl_down_sync(0xffffffffu, klt, off);
    __shared__ float sw[8];
    if ((threadIdx.x & 31) == 0) sw[threadIdx.x >> 5] = klt;
    __syncthreads();
    if (threadIdx.x == 0) {
        float s = 0;
        for (int j = 0; j < 8; j++) s += sw[j];
        atomicAdd(&d_sums[3], s);
    }
}

// ---------------- edge predictions + log sums ----------------
__global__ void __launch_bounds__(256) k_pred(const int* __restrict__ pe,
                                              const int* __restrict__ ne,
                                              float* __restrict__ out) {
    int gw = (blockIdx.x * 256 + threadIdx.x) >> 5;
    int lane = threadIdx.x & 31;
    int wib = threadIdx.x >> 5;
    bool isneg = gw >= EPN;
    int i = isneg ? gw - EPN : gw;
    const int* e = isneg ? ne : pe;
    int a = e[i], b = e[EPN + i];
    const float4* ra = (const float4*)(d_zl1 + (size_t)a * 256);
    const float4* rb = (const float4*)(d_zl2 + (size_t)b * 256);
    float s = 0.f;
#pragma unroll
    for (int q = 0; q < 2; q++) {
        float4 u = ra[lane + 32 * q], v = rb[lane + 32 * q];
        s += u.x * v.x + u.y * v.y + u.z * v.z + u.w * v.w;
    }
    for (int off = 16; off; off >>= 1) s += __shfl_down_sync(0xffffffffu, s, off);
    __shared__ float sl[8];
    if (lane == 0) {
        float p = 1.f / (1.f + expf(-s));
        out[2 + gw] = p;
        sl[wib] = isneg ? logf(1.f - p + 1e-15f) : logf(p + 1e-15f);
    }
    __syncthreads();
    if (threadIdx.x == 0) {
        float tt = 0;
        for (int j = 0; j < 8; j++) tt += sl[j];
        atomicAdd(isneg ? &d_sums[2] : &d_sums[1], tt);
    }
}

__global__ void k_final(float* __restrict__ out) {
    float rec = -(d_sums[1] / (float)EPN) - (d_sums[2] / (float)EPN);
    float kl = -0.5f * d_sums[3] / (float)G;
    out[0] = rec + kl / (float)G;
    out[1] = d_sums[0] / (float)G;
}

// ---------------- launch ----------------
extern "C" void kernel_launch(void* const* d_in, const int* in_sizes, int n_in,
                              void* d_out, int out_size) {
    const float* x   = (const float*)d_in[0];
    const int*   ei  = (const int*)d_in[1];
    const float* ew  = (const float*)d_in[2];
    const int*   pe  = (const int*)d_in[3];
    const int*   ne  = (const int*)d_in[4];
    const float* eps_= (const float*)d_in[5];
    const float* Wg  = (const float*)d_in[6];
    const float* bg  = (const float*)d_in[7];
    const float* Wf1 = (const float*)d_in[8];
    const float* bf1 = (const float*)d_in[9];
    const float* Wf2 = (const float*)d_in[10];
    const float* bf2 = (const float*)d_in[11];
    const float* Wc1 = (const float*)d_in[12];
    const float* bc1 = (const float*)d_in[13];
    const float* Wmu = (const float*)d_in[14];
    const float* bmu = (const float*)d_in[15];
    const float* Wls = (const float*)d_in[16];
    const float* bls = (const float*)d_in[17];
    const float* emb = (const float*)d_in[18];
    const float* Wl1 = (const float*)d_in[19];
    const float* bl1 = (const float*)d_in[20];
    const float* Wl2 = (const float*)d_in[21];
    const float* bl2 = (const float*)d_in[22];
    float* out = (float*)d_out;

    const int dyn_xw = 36864;
    cudaFuncSetAttribute(k_xwagg, cudaFuncAttributeMaxDynamicSharedMemorySize, dyn_xw);

    k_zero<<<1024, 256>>>(pe);
    k_prepw<<<234, 1024>>>(Wg, Wc1, Wmu, Wls, Wl1, Wl2, Wf1);
    k_prepfrag<<<8, 1024>>>();
    k_deg<<<EPN / 256, 256>>>(pe);
    k_xwagg<<<G, 256, dyn_xw>>>(x, ei, ew, bg, bf1, Wf2, bf2);
    k_dinv<<<G / 256, 256>>>();
    k_scatter<<<EPN * 32 / 256, 256>>>(pe, 0);
    // h = relu(agg1 @ Wc1 + bc1)   [4096x128]@[128x256]
    k_mma<<<dim3(2, 32), 256>>>(1, 128, 2, 8192, 8192, bc1, bc1, 1, 1, 256, 1, 1);
    k_scatter<<<EPN * 32 / 256, 256>>>(pe, 1);
    // mu | ls   [4096x256]@[256x128] x2 in one launch
    k_mma<<<dim3(2, 32), 256>>>(2, 256, 1, 40960, 73728, bmu, bls, 2, 3, 128, 0, 2);
    k_z<<<G * DD / 256, 256>>>(eps_, emb);
    // zl1 | zl2   [4096x256]@[256x256] x2 in one launch
    k_mma<<<dim3(4, 32), 256>>>(3, 256, 2, 106496, 172032, bl1, bl2, 4, 5, 256, 0, 0);
    k_pred<<<2 * EPN * 32 / 256, 256>>>(pe, ne, out);
    k_final<<<1, 1>>>(out);
}